// round 1
// baseline (speedup 1.0000x reference)
#include <cuda_runtime.h>

#define BB   4
#define NN   256
#define DIN  128
#define DE   64
#define NH   8
#define DK   16
#define HD   128   // NH*DK
#define JC   16    // j-chunk size

// Scratch for Q, K(prescaled), V projections (device globals: no allocation)
__device__ float g_Q[BB * NN * HD];
__device__ float g_K[BB * NN * HD];
__device__ float g_V[BB * NN * HD];

// ---------------------------------------------------------------------------
// Kernel 1: QKV projection. One block per (b,i) row, 128 threads.
//   Q[bi, t] = sum_d h[bi,d] * WQ[d,t]   (K scaled by DK^-0.5)
// ---------------------------------------------------------------------------
__global__ __launch_bounds__(128) void qkv_kernel(
    const float* __restrict__ h,
    const float* __restrict__ WQ,
    const float* __restrict__ WK,
    const float* __restrict__ WV)
{
    __shared__ float sh[DIN];
    const int bi = blockIdx.x;          // 0 .. B*N-1
    const int t  = threadIdx.x;         // 0 .. 127

    sh[t] = h[bi * DIN + t];
    __syncthreads();

    float q = 0.f, k = 0.f, v = 0.f;
    #pragma unroll 16
    for (int d = 0; d < DIN; d++) {
        const float hv = sh[d];
        q = fmaf(hv, WQ[d * HD + t], q);
        k = fmaf(hv, WK[d * HD + t], k);
        v = fmaf(hv, WV[d * HD + t], v);
    }
    g_Q[bi * HD + t] = q;
    g_K[bi * HD + t] = k * 0.25f;       // DK^-0.5 = 1/4
    g_V[bi * HD + t] = v;
}

// ---------------------------------------------------------------------------
// Kernel 2: fused edge-augmented attention. One block per (b,i), 256 threads.
//   Threads   0..127 ("A"): own WE2 column hk in regs; compute E2, s, denom.
//   Threads 128..255 ("B"): own WE  column hk in regs; compute E.
//   Both halves share accumulation of s*(V+E).
// ---------------------------------------------------------------------------
__global__ __launch_bounds__(256) void attn_kernel(
    const float* __restrict__ e,
    const float* __restrict__ mask,
    const float* __restrict__ WE,
    const float* __restrict__ WE2,
    float* __restrict__ out)
{
    __shared__ float sQrow[HD];
    __shared__ float sMask[NN];
    __shared__ float sQK[NN][NH];
    __shared__ float sed[JC][DE];
    __shared__ float sS [JC][HD];
    __shared__ float sEb[JC][HD];

    const int i = blockIdx.x;
    const int b = blockIdx.y;
    const int t = threadIdx.x;
    const bool isA = (t < HD);
    const int hk = isA ? t : (t - HD);

    // --- weight column into registers (64 floats) ---
    float w[DE];
    {
        const float* __restrict__ W = isA ? WE2 : WE;
        #pragma unroll
        for (int d = 0; d < DE; d++) w[d] = W[d * HD + hk];
    }

    // --- prologue: mask row, Q row ---
    sMask[t & (NN - 1)] = mask[b * NN + (t & (NN - 1))];
    if (t < HD) sQrow[t] = g_Q[(b * NN + i) * HD + t];
    __syncthreads();

    // --- qk[j][h] for all j: thread t handles j = t ---
    {
        const int j = t;
        const float4* __restrict__ Kp =
            (const float4*)(g_K + (size_t)(b * NN + j) * HD);
        #pragma unroll
        for (int hh = 0; hh < NH; hh++) {
            float s_ = 0.f;
            #pragma unroll
            for (int kk = 0; kk < DK / 4; kk++) {
                const float4 kv = Kp[hh * (DK / 4) + kk];
                const float* qp = &sQrow[hh * DK + kk * 4];
                s_ += kv.x * qp[0] + kv.y * qp[1] + kv.z * qp[2] + kv.w * qp[3];
            }
            sQK[j][hh] = s_;
        }
    }
    __syncthreads();

    const float mi = sMask[i];
    const int   hsel = hk >> 4;         // head index for group A
    float acc = 0.f;
    float denom = 0.f;

    for (int j0 = 0; j0 < NN; j0 += JC) {
        // cooperative load of e[b,i, j0:j0+JC, :]  (contiguous JC*DE floats)
        {
            const float4* __restrict__ ep =
                (const float4*)(e + ((size_t)(b * NN + i) * NN + j0) * DE);
            ((float4*)sed)[t] = ep[t];   // 256 float4 = JC*DE floats
        }
        __syncthreads();

        if (isA) {
            // E2 -> scores -> s ; accumulate denom
            for (int jj = 0; jj < JC; jj++) {
                float a0 = 0.f, a1 = 0.f, a2 = 0.f, a3 = 0.f;
                const float4* __restrict__ ev = (const float4*)sed[jj];
                #pragma unroll
                for (int d4 = 0; d4 < DE / 4; d4++) {
                    const float4 x = ev[d4];
                    a0 = fmaf(x.x, w[d4 * 4 + 0], a0);
                    a1 = fmaf(x.y, w[d4 * 4 + 1], a1);
                    a2 = fmaf(x.z, w[d4 * 4 + 2], a2);
                    a3 = fmaf(x.w, w[d4 * 4 + 3], a3);
                }
                const float e2 = (a0 + a1) + (a2 + a3);
                float sc = sQK[j0 + jj][hsel] + e2;
                sc = fminf(5.f, fmaxf(-5.f, sc));
                const float am = mi * sMask[j0 + jj];
                const float s1 = __expf(sc) * am;   // first mask multiply
                denom += s1;                         // denom uses single-mask scores
                sS[jj][hk] = s1 * am;                // second mask multiply (dropout id)
            }
        } else {
            // E columns
            for (int jj = 0; jj < JC; jj++) {
                float a0 = 0.f, a1 = 0.f, a2 = 0.f, a3 = 0.f;
                const float4* __restrict__ ev = (const float4*)sed[jj];
                #pragma unroll
                for (int d4 = 0; d4 < DE / 4; d4++) {
                    const float4 x = ev[d4];
                    a0 = fmaf(x.x, w[d4 * 4 + 0], a0);
                    a1 = fmaf(x.y, w[d4 * 4 + 1], a1);
                    a2 = fmaf(x.z, w[d4 * 4 + 2], a2);
                    a3 = fmaf(x.w, w[d4 * 4 + 3], a3);
                }
                sEb[jj][hk] = (a0 + a1) + (a2 + a3);
            }
        }
        __syncthreads();

        // accumulate s * (V + E): A takes first half of chunk, B second half
        {
            const int jbase = isA ? 0 : (JC / 2);
            const float* __restrict__ Vb =
                g_V + (size_t)(b * NN + j0 + jbase) * HD + hk;
            #pragma unroll
            for (int jj = 0; jj < JC / 2; jj++) {
                const float s = sS[jbase + jj][hk];
                const float vv = Vb[(size_t)jj * HD];
                acc = fmaf(s, vv + sEb[jbase + jj][hk], acc);
            }
        }
        __syncthreads();   // protect sed/sS/sEb before next chunk overwrites
    }

    // --- combine halves and write out ---
    if (!isA) sEb[0][hk] = acc;
    __syncthreads();
    if (isA) {
        const float tot = acc + sEb[0][hk];
        out[((size_t)(b * NN) + i) * HD + hk] = tot / fmaxf(denom, 1e-6f);
    }
}

// ---------------------------------------------------------------------------
// Launch
// ---------------------------------------------------------------------------
extern "C" void kernel_launch(void* const* d_in, const int* in_sizes, int n_in,
                              void* d_out, int out_size)
{
    const float* h    = (const float*)d_in[0];
    const float* e    = (const float*)d_in[1];
    const float* mask = (const float*)d_in[2];
    const float* WQ   = (const float*)d_in[3];
    const float* WK   = (const float*)d_in[4];
    const float* WV   = (const float*)d_in[5];
    const float* WE   = (const float*)d_in[6];
    const float* WE2  = (const float*)d_in[7];
    float* out = (float*)d_out;

    qkv_kernel<<<BB * NN, 128>>>(h, WQ, WK, WV);

    dim3 grid(NN, BB);
    attn_kernel<<<grid, 256>>>(e, mask, WE, WE2, out);
}

// round 8
// speedup vs baseline: 2.4635x; 2.4635x over previous
#include <cuda_runtime.h>
#include <cuda_bf16.h>
#include <cstdint>

#define BB   4
#define NN   256
#define DIN  128
#define DE   64
#define NH   8
#define DK   16
#define HD   128

// ---------------------------------------------------------------------------
// device-global scratch (no allocations allowed)
// ---------------------------------------------------------------------------
__device__ float g_Q[BB * NN * HD];
__device__ float g_K[BB * NN * HD];   // pre-scaled by DK^-0.5
__device__ float g_V[BB * NN * HD];
__device__ __nv_bfloat16 g_Bhi[2 * HD * DE];  // [n=256][d=64]: n<128 -> WE2 col n, else WE col n-128
__device__ __nv_bfloat16 g_Blo[2 * HD * DE];

#define SMEM_SWZ(off) ((off) ^ (((off) >> 3) & 0x70))

// ---------------------------------------------------------------------------
// warp-level bf16 MMA (sm_80+ PTX, legal on plain sm_103 target)
// D(16x8,f32) += A(16x16,row) * B(16x8,col)
// ---------------------------------------------------------------------------
__device__ __forceinline__ void mma16816(float* c, const uint32_t* a, const uint32_t* b) {
    asm volatile(
        "mma.sync.aligned.m16n8k16.row.col.f32.bf16.bf16.f32 "
        "{%0,%1,%2,%3}, {%4,%5,%6,%7}, {%8,%9}, {%0,%1,%2,%3};"
        : "+f"(c[0]), "+f"(c[1]), "+f"(c[2]), "+f"(c[3])
        : "r"(a[0]), "r"(a[1]), "r"(a[2]), "r"(a[3]), "r"(b[0]), "r"(b[1]));
}

// ---------------------------------------------------------------------------
// SMEM layout (dynamic). W region persists; A region is overlaid by staging.
// ---------------------------------------------------------------------------
#define SM_B       0                       // Whi 32768, Wlo at +32768  -> [0, 65536)
#define SM_A       65536                   // Ahi 32768, Alo at +32768  -> ends 131072 (dead after frag load)
#define SM_P       65536                   // p1 staging 64*257*4 = 65792 (overlays A)
#define SM_E       (SM_P + 65792)          // E  staging 65792 -> ends 197120
#define SM_QK      197120                  // 256*9*4 = 9216
#define SM_AM      206336                  // 256*4
#define SM_QROW    207360                  // 128*4
#define SM_REDD    207872                  // 256*4
#define SM_REDO    208896                  // 256*4
#define SMEM_TOTAL 209920

// ---------------------------------------------------------------------------
// Kernel 1: QKV projection (fp32, exact). One block per (b,i), 128 threads.
// ---------------------------------------------------------------------------
__global__ __launch_bounds__(128) void qkv_kernel(
    const float* __restrict__ h,
    const float* __restrict__ WQ,
    const float* __restrict__ WK,
    const float* __restrict__ WV)
{
    __shared__ float sh[DIN];
    const int bi = blockIdx.x;
    const int t  = threadIdx.x;
    sh[t] = h[bi * DIN + t];
    __syncthreads();
    float q = 0.f, k = 0.f, v = 0.f;
    #pragma unroll 16
    for (int d = 0; d < DIN; d++) {
        const float hv = sh[d];
        q = fmaf(hv, WQ[d * HD + t], q);
        k = fmaf(hv, WK[d * HD + t], k);
        v = fmaf(hv, WV[d * HD + t], v);
    }
    g_Q[bi * HD + t] = q;
    g_K[bi * HD + t] = k * 0.25f;
    g_V[bi * HD + t] = v;
}

// ---------------------------------------------------------------------------
// Kernel 2: weight split -> layout [n][d], bf16 hi/lo
// ---------------------------------------------------------------------------
__global__ __launch_bounds__(256) void conv_w_kernel(
    const float* __restrict__ WE, const float* __restrict__ WE2)
{
    const int idx = blockIdx.x * 256 + threadIdx.x;   // 0..16383
    const int n = idx >> 6, d = idx & 63;
    const float* W = (n < HD) ? WE2 : WE;
    const float w = W[d * HD + (n & (HD - 1))];
    const __nv_bfloat16 hi = __float2bfloat16(w);
    const __nv_bfloat16 lo = __float2bfloat16(w - __bfloat162float(hi));
    g_Bhi[idx] = hi;
    g_Blo[idx] = lo;
}

// ---------------------------------------------------------------------------
// Kernel 3: fused HMMA attention. One CTA per (b,i), 256 threads (8 warps).
//   S[256j x 256n] = [e_hi|e_lo|e_hi] @ [Whi;Whi;Wlo]^T  (3-term bf16 split)
//   cols n<128: E2 scores; cols n>=128: E.  Warp w owns j rows 32w..32w+31.
// ---------------------------------------------------------------------------
__global__ __launch_bounds__(256, 1)
void attn_mma_kernel(
    const float* __restrict__ e,
    const float* __restrict__ mask,
    float* __restrict__ out)
{
    extern __shared__ char smem[];
    const int t   = threadIdx.x;
    const int wid = t >> 5;
    const int lid = t & 31;
    const int gid = lid >> 2;        // 0..7
    const int tig = lid & 3;         // 0..3
    const int bi  = blockIdx.x;
    const int b   = bi >> 8;
    const int i   = bi & 255;

    float* sQKv  = (float*)(smem + SM_QK);
    float* sAmv  = (float*)(smem + SM_AM);
    float* sQrow = (float*)(smem + SM_QROW);
    float* sPv   = (float*)(smem + SM_P);
    float* sEv   = (float*)(smem + SM_E);
    float* sRedD = (float*)(smem + SM_REDD);
    float* sRedO = (float*)(smem + SM_REDO);

    // ---- load W (bf16 hi/lo) into SW128 smem: [256 rows x 128B] ----
    {
        const int ch = t & 7;          // 16B chunk within 128B row
        const int r0 = t >> 3;         // 32 rows per iteration
        #pragma unroll
        for (int it = 0; it < 8; it++) {
            const int row = it * 32 + r0;
            const uint32_t off = SMEM_SWZ(row * 128 + ch * 16);
            *(uint4*)(smem + SM_B + off)         = ((const uint4*)g_Bhi)[row * 8 + ch];
            *(uint4*)(smem + SM_B + 32768 + off) = ((const uint4*)g_Blo)[row * 8 + ch];
        }
    }

    // ---- load A: e[b,i,j,:] fp32 -> split bf16 hi/lo, SW128 smem ----
    {
        const float* __restrict__ eb = e + (size_t)bi * NN * DE;
        const int ch = t & 15;         // 4-float chunk within 64-float row
        const int r0 = t >> 4;         // 16 rows per iteration
        #pragma unroll
        for (int it = 0; it < 16; it++) {
            const int row = it * 16 + r0;
            const float4 v = ((const float4*)(eb + row * DE))[ch];
            const __nv_bfloat16 hx = __float2bfloat16(v.x);
            const __nv_bfloat16 hy = __float2bfloat16(v.y);
            const __nv_bfloat16 hz = __float2bfloat16(v.z);
            const __nv_bfloat16 hw = __float2bfloat16(v.w);
            const __nv_bfloat16 lx = __float2bfloat16(v.x - __bfloat162float(hx));
            const __nv_bfloat16 ly = __float2bfloat16(v.y - __bfloat162float(hy));
            const __nv_bfloat16 lz = __float2bfloat16(v.z - __bfloat162float(hz));
            const __nv_bfloat16 lw = __float2bfloat16(v.w - __bfloat162float(hw));
            __nv_bfloat162 h01; h01.x = hx; h01.y = hy;
            __nv_bfloat162 h23; h23.x = hz; h23.y = hw;
            __nv_bfloat162 l01; l01.x = lx; l01.y = ly;
            __nv_bfloat162 l23; l23.x = lz; l23.y = lw;
            uint2 hv; hv.x = *(uint32_t*)&h01; hv.y = *(uint32_t*)&h23;
            uint2 lv; lv.x = *(uint32_t*)&l01; lv.y = *(uint32_t*)&l23;
            const uint32_t off = SMEM_SWZ(row * 128 + ch * 8);
            *(uint2*)(smem + SM_A + off)         = hv;
            *(uint2*)(smem + SM_A + 32768 + off) = lv;
        }
    }

    // ---- mask products + Q row ----
    sAmv[t] = mask[b * NN + i] * mask[b * NN + t];
    if (t < HD) sQrow[t] = g_Q[(size_t)bi * HD + t];
    __syncthreads();

    // ---- QK scores (fp32 exact): thread t owns j = t ----
    {
        const float4* __restrict__ Kp = (const float4*)(g_K + ((size_t)b * NN + t) * HD);
        #pragma unroll
        for (int hh = 0; hh < NH; hh++) {
            float s_ = 0.f;
            #pragma unroll
            for (int kk = 0; kk < DK / 4; kk++) {
                const float4 kv = Kp[hh * (DK / 4) + kk];
                const float* qp = &sQrow[hh * DK + kk * 4];
                s_ += kv.x * qp[0] + kv.y * qp[1] + kv.z * qp[2] + kv.w * qp[3];
            }
            sQKv[t * 9 + hh] = s_;
        }
    }
    __syncthreads();

    // ---- A fragments into registers: [mblk][kstep][hi/lo][4] ----
    uint32_t afr[2][4][2][4];
    {
        const int jb = wid * 32;
        #pragma unroll
        for (int mblk = 0; mblk < 2; mblk++) {
            const int r0 = jb + mblk * 16 + gid;
            #pragma unroll
            for (int ks = 0; ks < 4; ks++) {
                const uint32_t o0 = SMEM_SWZ((uint32_t)(r0 * 128 + ks * 32))            + tig * 4;
                const uint32_t o1 = SMEM_SWZ((uint32_t)((r0 + 8) * 128 + ks * 32))      + tig * 4;
                const uint32_t o2 = SMEM_SWZ((uint32_t)(r0 * 128 + ks * 32 + 16))       + tig * 4;
                const uint32_t o3 = SMEM_SWZ((uint32_t)((r0 + 8) * 128 + ks * 32 + 16)) + tig * 4;
                afr[mblk][ks][0][0] = *(const uint32_t*)(smem + SM_A + o0);
                afr[mblk][ks][0][1] = *(const uint32_t*)(smem + SM_A + o1);
                afr[mblk][ks][0][2] = *(const uint32_t*)(smem + SM_A + o2);
                afr[mblk][ks][0][3] = *(const uint32_t*)(smem + SM_A + o3);
                afr[mblk][ks][1][0] = *(const uint32_t*)(smem + SM_A + 32768 + o0);
                afr[mblk][ks][1][1] = *(const uint32_t*)(smem + SM_A + 32768 + o1);
                afr[mblk][ks][1][2] = *(const uint32_t*)(smem + SM_A + 32768 + o2);
                afr[mblk][ks][1][3] = *(const uint32_t*)(smem + SM_A + 32768 + o3);
            }
        }
    }
    // per-thread mask values for the 4 j rows this thread's frags cover
    float am4[2][2];
    #pragma unroll
    for (int mblk = 0; mblk < 2; mblk++) {
        am4[mblk][0] = sAmv[wid * 32 + mblk * 16 + gid];
        am4[mblk][1] = sAmv[wid * 32 + mblk * 16 + gid + 8];
    }
    __syncthreads();   // ALL A frags in regs before staging overwrites A region

    // ---- main loop: two 64-col halves ----
    for (int h0 = 0; h0 < HD; h0 += 64) {
        // phase 1: HMMA scores + E, fragment epilogue -> staging
        #pragma unroll 1
        for (int cg = 0; cg < 8; cg++) {
            float accS[2][4] = {{0.f,0.f,0.f,0.f},{0.f,0.f,0.f,0.f}};
            float accE[2][4] = {{0.f,0.f,0.f,0.f},{0.f,0.f,0.f,0.f}};
            const int n_s = h0 + cg * 8 + gid;        // score col for B frag
            const int n_e = n_s + 128;                // E col
            #pragma unroll
            for (int ks = 0; ks < 4; ks++) {
                const uint32_t os0 = SMEM_SWZ((uint32_t)(n_s * 128 + ks * 32))      + tig * 4;
                const uint32_t os1 = SMEM_SWZ((uint32_t)(n_s * 128 + ks * 32 + 16)) + tig * 4;
                const uint32_t oe0 = SMEM_SWZ((uint32_t)(n_e * 128 + ks * 32))      + tig * 4;
                const uint32_t oe1 = SMEM_SWZ((uint32_t)(n_e * 128 + ks * 32 + 16)) + tig * 4;
                uint32_t bsh[2], bsl[2], beh[2], bel[2];
                bsh[0] = *(const uint32_t*)(smem + SM_B + os0);
                bsh[1] = *(const uint32_t*)(smem + SM_B + os1);
                bsl[0] = *(const uint32_t*)(smem + SM_B + 32768 + os0);
                bsl[1] = *(const uint32_t*)(smem + SM_B + 32768 + os1);
                beh[0] = *(const uint32_t*)(smem + SM_B + oe0);
                beh[1] = *(const uint32_t*)(smem + SM_B + oe1);
                bel[0] = *(const uint32_t*)(smem + SM_B + 32768 + oe0);
                bel[1] = *(const uint32_t*)(smem + SM_B + 32768 + oe1);
                #pragma unroll
                for (int mblk = 0; mblk < 2; mblk++) {
                    mma16816(accS[mblk], afr[mblk][ks][0], bsh);  // Ahi*Whi
                    mma16816(accS[mblk], afr[mblk][ks][1], bsh);  // Alo*Whi
                    mma16816(accS[mblk], afr[mblk][ks][0], bsl);  // Ahi*Wlo
                    mma16816(accE[mblk], afr[mblk][ks][0], beh);
                    mma16816(accE[mblk], afr[mblk][ks][1], beh);
                    mma16816(accE[mblk], afr[mblk][ks][0], bel);
                }
            }
            // fragment epilogue: clip/exp/mask -> staging
            #pragma unroll
            for (int mblk = 0; mblk < 2; mblk++) {
                #pragma unroll
                for (int u = 0; u < 4; u++) {
                    const int j  = wid * 32 + mblk * 16 + gid + (u >> 1) * 8;
                    const int cn = cg * 8 + tig * 2 + (u & 1);
                    const int head = (h0 + cn) >> 4;
                    float s = sQKv[j * 9 + head] + accS[mblk][u];
                    s = fminf(5.f, fmaxf(-5.f, s));
                    const float p1 = __expf(s) * am4[mblk][u >> 1];
                    sPv[cn * 257 + j] = p1;
                    sEv[cn * 257 + j] = accE[mblk][u];
                }
            }
        }
        __syncthreads();

        // phase 2: column reductions (thread: col c = t&63, j-group g = t>>6)
        {
            const int c = t & 63, g = t >> 6;
            const int hk = h0 + c;
            float den = 0.f, o = 0.f;
            const float* __restrict__ Vp = g_V + ((size_t)b * NN + g * 64) * HD + hk;
            #pragma unroll 8
            for (int jj = 0; jj < 64; jj++) {
                const int j2 = g * 64 + jj;
                const float p1 = sPv[c * 257 + j2];
                den += p1;
                o = fmaf(p1 * sAmv[j2], Vp[(size_t)jj * HD] + sEv[c * 257 + j2], o);
            }
            sRedD[g * 64 + c] = den;
            sRedO[g * 64 + c] = o;
        }
        __syncthreads();
        if (t < 64) {
            float D_ = 0.f, O_ = 0.f;
            #pragma unroll
            for (int g4 = 0; g4 < 4; g4++) {
                D_ += sRedD[g4 * 64 + t];
                O_ += sRedO[g4 * 64 + t];
            }
            out[(size_t)bi * HD + h0 + t] = O_ / fmaxf(D_, 1e-6f);
        }
        __syncthreads();   // before staging reuse
    }
}

// ---------------------------------------------------------------------------
// Launch
// ---------------------------------------------------------------------------
extern "C" void kernel_launch(void* const* d_in, const int* in_sizes, int n_in,
                              void* d_out, int out_size)
{
    const float* h    = (const float*)d_in[0];
    const float* e    = (const float*)d_in[1];
    const float* mask = (const float*)d_in[2];
    const float* WQ   = (const float*)d_in[3];
    const float* WK   = (const float*)d_in[4];
    const float* WV   = (const float*)d_in[5];
    const float* WE   = (const float*)d_in[6];
    const float* WE2  = (const float*)d_in[7];
    float* out = (float*)d_out;

    cudaFuncSetAttribute(attn_mma_kernel,
                         cudaFuncAttributeMaxDynamicSharedMemorySize, SMEM_TOTAL);

    qkv_kernel<<<BB * NN, 128>>>(h, WQ, WK, WV);
    conv_w_kernel<<<64, 256>>>(WE, WE2);
    attn_mma_kernel<<<BB * NN, 256, SMEM_TOTAL>>>(e, mask, out);
}